// round 17
// baseline (speedup 1.0000x reference)
#include <cuda_runtime.h>
#include <math.h>

#define B_ 4
#define M_ 2048
#define E_ 1024
#define D_ 256
#define H_ 8
#define DH_ 32
#define SPLITK 4
#define KCH (M_ / SPLITK)   // 512

// ---------------- scratch (device globals: allocation-free) ----------------
__device__ float g_q[B_*H_*M_*DH_];
__device__ float g_k[B_*H_*M_*DH_];
__device__ float g_v[B_*H_*M_*DH_];
__device__ float g_attn[B_*M_*D_];
__device__ float g_attnout[B_*M_*D_];
__device__ float g_Spart[SPLITK*B_*E_*D_];   // TRANSPOSED: [sk][b][d][e]
__device__ float g_ef[B_*E_*D_];             // TRANSPOSED: [b][d][e]
__device__ float g_ef2[B_*E_*D_];            // normal [b][e][dout]

// ---------------- helpers ---------------------------------------------------
__device__ __forceinline__ void mma16(float* d, const unsigned* a, const unsigned* b) {
    asm volatile(
        "mma.sync.aligned.m16n8k16.row.col.f32.f16.f16.f32 "
        "{%0,%1,%2,%3},{%4,%5,%6,%7},{%8,%9},{%0,%1,%2,%3};"
        : "+f"(d[0]), "+f"(d[1]), "+f"(d[2]), "+f"(d[3])
        : "r"(a[0]), "r"(a[1]), "r"(a[2]), "r"(a[3]), "r"(b[0]), "r"(b[1]));
}
__device__ __forceinline__ unsigned pk16(float lo, float hi) {
    unsigned r;
    asm("cvt.rn.f16x2.f32 %0, %1, %2;" : "=r"(r) : "f"(hi), "f"(lo));
    return r;
}

// ---------------- NT fp16 GEMM: C[M,N] = A[M,K] @ Bw[N,K]^T (+bias) --------
#define NTSTR 20
template<int EPI>
__global__ __launch_bounds__(256, 2)
void gemm_nt_f16(const float* __restrict__ A, const float* __restrict__ Bw,
                 const float* __restrict__ bias, float* __restrict__ C,
                 int M, int N, int K)
{
    __shared__ unsigned As[128*NTSTR];
    __shared__ unsigned Bs[128*NTSTR];
    const int t = threadIdx.x, lane = t & 31, w = t >> 5;
    const int m0 = blockIdx.y * 128, n0 = blockIdx.x * 128;
    const int wm = (w & 1) * 64, wn = (w >> 1) * 32;
    const int g = lane >> 2, qt = lane & 3;

    float acc[4][4][4];
#pragma unroll
    for (int i = 0; i < 4; i++)
#pragma unroll
        for (int j = 0; j < 4; j++)
#pragma unroll
            for (int r = 0; r < 4; r++) acc[i][j][r] = 0.f;

    for (int k0 = 0; k0 < K; k0 += 32) {
#pragma unroll
        for (int p = 0; p < 4; p++) {
            int lin = p * 1024 + t * 4;
            int r = lin >> 5, c = lin & 31;
            float4 av = *(const float4*)(A + (size_t)(m0 + r) * K + k0 + c);
            As[r*NTSTR + c/2]     = pk16(av.x, av.y);
            As[r*NTSTR + c/2 + 1] = pk16(av.z, av.w);
            float4 bv = *(const float4*)(Bw + (size_t)(n0 + r) * K + k0 + c);
            Bs[r*NTSTR + c/2]     = pk16(bv.x, bv.y);
            Bs[r*NTSTR + c/2 + 1] = pk16(bv.z, bv.w);
        }
        __syncthreads();
#pragma unroll
        for (int ks = 0; ks < 2; ks++) {
            const int kw = ks * 8 + qt;
            unsigned af[4][4], bf[4][2];
#pragma unroll
            for (int mt = 0; mt < 4; mt++) {
                const int mr = wm + mt * 16 + g;
                af[mt][0] = As[mr*NTSTR + kw];
                af[mt][1] = As[(mr+8)*NTSTR + kw];
                af[mt][2] = As[mr*NTSTR + kw + 4];
                af[mt][3] = As[(mr+8)*NTSTR + kw + 4];
            }
#pragma unroll
            for (int nt = 0; nt < 4; nt++) {
                const int nr = wn + nt * 8 + g;
                bf[nt][0] = Bs[nr*NTSTR + kw];
                bf[nt][1] = Bs[nr*NTSTR + kw + 4];
            }
#pragma unroll
            for (int mt = 0; mt < 4; mt++)
#pragma unroll
                for (int nt = 0; nt < 4; nt++)
                    mma16(acc[mt][nt], af[mt], bf[nt]);
        }
        __syncthreads();
    }

#pragma unroll
    for (int mt = 0; mt < 4; mt++) {
#pragma unroll
        for (int nt = 0; nt < 4; nt++) {
            const int n = n0 + wn + nt * 8 + 2 * qt;
            float b0 = bias ? bias[n] : 0.f;
            float b1 = bias ? bias[n+1] : 0.f;
#pragma unroll
            for (int rh = 0; rh < 2; rh++) {
                const int m = m0 + wm + mt * 16 + g + rh * 8;
                float v0 = acc[mt][nt][rh*2] + b0;
                float v1 = acc[mt][nt][rh*2+1] + b1;
                if (EPI == 0) {
                    *(float2*)(C + (size_t)m * N + n) = make_float2(v0, v1);
                } else {
                    int bi = m >> 11, mm = m & (M_ - 1);
                    int which = n >> 8, dd = n & 255;
                    int h = dd >> 5, c = dd & 31;
                    float* dst = (which == 0 ? g_q : which == 1 ? g_k : g_v)
                               + (size_t)(((bi << 3) + h) * M_ + mm) * DH_ + c;
                    *(float2*)dst = make_float2(v0, v1);
                }
            }
        }
    }
}

// ---------------- TN fp16 GEMM (split-K): S^T partials, A reg-prefetched ---
#define TNSTR 68
__global__ __launch_bounds__(256, 2)
void gemm_tn_S_f16(const float* __restrict__ inc)
{
    __shared__ unsigned As[32*TNSTR];
    __shared__ unsigned Bs[32*TNSTR];
    const int t = threadIdx.x, lane = t & 31, w = t >> 5;
    const int z = blockIdx.z;
    const int b = z >> 2, sk = z & 3;
    const int e0 = blockIdx.y * 128, d0 = blockIdx.x * 128;
    const int kbase = sk * KCH;
    const int wm = (w & 1) * 64, wn = (w >> 1) * 32;
    const int g = lane >> 2, qt = lane & 3;
    const float* Ag = inc       + (size_t)b * M_ * E_;
    const float* Bg = g_attnout + (size_t)b * M_ * D_;

    const unsigned abase = (unsigned)__cvta_generic_to_shared(As);
    const unsigned bbase = (unsigned)__cvta_generic_to_shared(Bs);
    const int il = lane & 7, qq = lane >> 3;
    const int q2 = (lane >> 3) & 1;

    float acc[4][4][4];
#pragma unroll
    for (int i = 0; i < 4; i++)
#pragma unroll
        for (int j = 0; j < 4; j++)
#pragma unroll
            for (int r = 0; r < 4; r++) acc[i][j][r] = 0.f;

    // per-thread A load coords (4 float4 per stage)
    const int lr0 = (t * 4) >> 7, lc0 = (t * 4) & 127;   // +p*8 rows

    // prologue: prefetch stage 0 A into registers
    float4 avr[4];
#pragma unroll
    for (int p = 0; p < 4; p++)
        avr[p] = *(const float4*)(Ag + (size_t)(kbase + lr0 + p*8) * E_ + e0 + lc0);

    const int NIT = KCH / 32;   // 16
    for (int it = 0; it < NIT; it++) {
        const int k0 = it * 32;
        // store prefetched A; load+store B directly (L2-resident)
#pragma unroll
        for (int p = 0; p < 4; p++) {
            int r = lr0 + p*8, c = lc0;
            As[r*TNSTR + c/2]     = pk16(avr[p].x, avr[p].y);
            As[r*TNSTR + c/2 + 1] = pk16(avr[p].z, avr[p].w);
            float4 bv = *(const float4*)(Bg + (size_t)(kbase + k0 + r) * D_ + d0 + c);
            Bs[r*TNSTR + c/2]     = pk16(bv.x, bv.y);
            Bs[r*TNSTR + c/2 + 1] = pk16(bv.z, bv.w);
        }
        __syncthreads();
        // prefetch next stage A (DRAM latency hidden behind mma below)
        if (it + 1 < NIT) {
#pragma unroll
            for (int p = 0; p < 4; p++)
                avr[p] = *(const float4*)(Ag + (size_t)(kbase + k0 + 32 + lr0 + p*8) * E_
                                          + e0 + lc0);
        }
#pragma unroll
        for (int ks = 0; ks < 2; ks++) {
            const int kc0 = ks * 16;
            unsigned af[4][4], bf[4][2];
#pragma unroll
            for (int mt = 0; mt < 4; mt++) {
                const int ecol = wm + mt * 16 + (qq & 1) * 8;
                unsigned ad = abase
                    + (unsigned)((kc0 + (qq >> 1) * 8 + il) * (TNSTR*4) + ecol * 2);
                asm volatile(
                    "ldmatrix.sync.aligned.m8n8.x4.trans.shared.b16 "
                    "{%0,%1,%2,%3},[%4];"
                    : "=r"(af[mt][0]), "=r"(af[mt][1]),
                      "=r"(af[mt][2]), "=r"(af[mt][3]) : "r"(ad));
            }
#pragma unroll
            for (int nt = 0; nt < 4; nt++) {
                const int ncol = wn + nt * 8;
                unsigned ad = bbase
                    + (unsigned)((kc0 + q2 * 8 + il) * (TNSTR*4) + ncol * 2);
                asm volatile(
                    "ldmatrix.sync.aligned.m8n8.x2.trans.shared.b16 "
                    "{%0,%1},[%2];"
                    : "=r"(bf[nt][0]), "=r"(bf[nt][1]) : "r"(ad));
            }
#pragma unroll
            for (int mt = 0; mt < 4; mt++)
#pragma unroll
                for (int nt = 0; nt < 4; nt++)
                    mma16(acc[mt][nt], af[mt], bf[nt]);
        }
        __syncthreads();
    }

    // transposed store: Cp[d][e]
    float* Cp = g_Spart + (size_t)(sk * B_ + b) * E_ * D_;
#pragma unroll
    for (int mt = 0; mt < 4; mt++)
#pragma unroll
        for (int nt = 0; nt < 4; nt++) {
            const int d = d0 + wn + nt * 8 + 2 * qt;
#pragma unroll
            for (int rh = 0; rh < 2; rh++) {
                const int e = e0 + wm + mt * 16 + g + rh * 8;
                Cp[(size_t)d * E_ + e]       = acc[mt][nt][rh*2];
                Cp[(size_t)(d+1) * E_ + e]   = acc[mt][nt][rh*2+1];
            }
        }
}

// ---------------- fused split-K reduce + softmax over e + ef = S*W ---------
__global__ void softmax_fused()
{
    const int t = threadIdx.x, lane = t & 31, wid = t >> 5;
    const int col = blockIdx.x * 8 + wid;
    const int b = col >> 8, d = col & 255;
    const size_t NB = (size_t)B_ * E_ * D_;
    const float* p0 = g_Spart + (size_t)b * E_ * D_ + (size_t)d * E_;

    float4 v[8];
    float mx = -1e30f;
#pragma unroll
    for (int r = 0; r < 8; r++) {
        const int e4 = lane + r * 32;
        float4 a = *(const float4*)(p0 + e4*4);
        float4 b1 = *(const float4*)(p0 + NB + e4*4);
        float4 c = *(const float4*)(p0 + 2*NB + e4*4);
        float4 dd = *(const float4*)(p0 + 3*NB + e4*4);
        float4 s = make_float4(a.x+b1.x+c.x+dd.x, a.y+b1.y+c.y+dd.y,
                               a.z+b1.z+c.z+dd.z, a.w+b1.w+c.w+dd.w);
        v[r] = s;
        mx = fmaxf(mx, fmaxf(fmaxf(s.x, s.y), fmaxf(s.z, s.w)));
    }
#pragma unroll
    for (int off = 16; off; off >>= 1) mx = fmaxf(mx, __shfl_xor_sync(~0u, mx, off));

    float4 ev[8];
    float se = 0.f;
#pragma unroll
    for (int r = 0; r < 8; r++) {
        ev[r].x = __expf(v[r].x - mx); ev[r].y = __expf(v[r].y - mx);
        ev[r].z = __expf(v[r].z - mx); ev[r].w = __expf(v[r].w - mx);
        se += ev[r].x + ev[r].y + ev[r].z + ev[r].w;
    }
#pragma unroll
    for (int off = 16; off; off >>= 1) se += __shfl_xor_sync(~0u, se, off);
    const float inv = 1.f / se;

    float* ob = g_ef + (size_t)b * E_ * D_ + (size_t)d * E_;
#pragma unroll
    for (int r = 0; r < 8; r++) {
        const int e4 = lane + r * 32;
        *(float4*)(ob + e4*4) = make_float4(v[r].x*ev[r].x*inv, v[r].y*ev[r].y*inv,
                                            v[r].z*ev[r].z*inv, v[r].w*ev[r].w*inv);
    }
}

// ---------------- hybrid TN proj: C[e][n] = efT[k=d][e] ^T @ projw[n][k]^T --
__global__ __launch_bounds__(256, 2)
void gemm_proj_f16(const float* __restrict__ Bw, float* __restrict__ C)
{
    __shared__ unsigned As[32*TNSTR];
    __shared__ unsigned Bs[128*NTSTR];
    const int t = threadIdx.x, lane = t & 31, w = t >> 5;
    const int b = blockIdx.z;
    const int m0 = blockIdx.y * 128, n0 = blockIdx.x * 128;
    const int wm = (w & 1) * 64, wn = (w >> 1) * 32;
    const int g = lane >> 2, qt = lane & 3;
    const float* Ag = g_ef + (size_t)b * E_ * D_;

    const unsigned abase = (unsigned)__cvta_generic_to_shared(As);
    const int il = lane & 7, qq = lane >> 3;

    float acc[4][4][4];
#pragma unroll
    for (int i = 0; i < 4; i++)
#pragma unroll
        for (int j = 0; j < 4; j++)
#pragma unroll
            for (int r = 0; r < 4; r++) acc[i][j][r] = 0.f;

    for (int k0 = 0; k0 < D_; k0 += 32) {
#pragma unroll
        for (int p = 0; p < 4; p++) {
            int lin = p * 1024 + t * 4;
            int r = lin >> 7, c = lin & 127;
            float4 av = *(const float4*)(Ag + (size_t)(k0 + r) * E_ + m0 + c);
            As[r*TNSTR + c/2]     = pk16(av.x, av.y);
            As[r*TNSTR + c/2 + 1] = pk16(av.z, av.w);
        }
#pragma unroll
        for (int p = 0; p < 4; p++) {
            int lin = p * 1024 + t * 4;
            int r = lin >> 5, c = lin & 31;
            float4 bv = *(const float4*)(Bw + (size_t)(n0 + r) * D_ + k0 + c);
            Bs[r*NTSTR + c/2]     = pk16(bv.x, bv.y);
            Bs[r*NTSTR + c/2 + 1] = pk16(bv.z, bv.w);
        }
        __syncthreads();
#pragma unroll
        for (int ks = 0; ks < 2; ks++) {
            const int kc0 = ks * 16;
            const int kw = ks * 8 + qt;
            unsigned af[4][4], bf[4][2];
#pragma unroll
            for (int mt = 0; mt < 4; mt++) {
                const int ecol = wm + mt * 16 + (qq & 1) * 8;
                unsigned ad = abase
                    + (unsigned)((kc0 + (qq >> 1) * 8 + il) * (TNSTR*4) + ecol * 2);
                asm volatile(
                    "ldmatrix.sync.aligned.m8n8.x4.trans.shared.b16 "
                    "{%0,%1,%2,%3},[%4];"
                    : "=r"(af[mt][0]), "=r"(af[mt][1]),
                      "=r"(af[mt][2]), "=r"(af[mt][3]) : "r"(ad));
            }
#pragma unroll
            for (int nt = 0; nt < 4; nt++) {
                const int nr = wn + nt * 8 + g;
                bf[nt][0] = Bs[nr*NTSTR + kw];
                bf[nt][1] = Bs[nr*NTSTR + kw + 4];
            }
#pragma unroll
            for (int mt = 0; mt < 4; mt++)
#pragma unroll
                for (int nt = 0; nt < 4; nt++)
                    mma16(acc[mt][nt], af[mt], bf[nt]);
        }
        __syncthreads();
    }

    float* Cb = C + (size_t)b * E_ * D_;
#pragma unroll
    for (int mt = 0; mt < 4; mt++)
#pragma unroll
        for (int nt = 0; nt < 4; nt++) {
            const int n = n0 + wn + nt * 8 + 2 * qt;
#pragma unroll
            for (int rh = 0; rh < 2; rh++) {
                const int m = m0 + wm + mt * 16 + g + rh * 8;
                *(float2*)(Cb + (size_t)m * D_ + n) =
                    make_float2(acc[mt][nt][rh*2], acc[mt][nt][rh*2+1]);
            }
        }
}

// ---------------- flash attention: full fp16, 256-thr single-wave ----------
// grid (8, 32), block 256 (8 warps x 32 q). 256 blocks <= 296 slots @ occ 2
// -> single wave; K/V tile reused over 256 queries (L2 traffic halved).
#define FTK 64
#define KVW 20

__global__ __launch_bounds__(256, 2)
void flash_attn_f16()
{
    __shared__ __align__(16) unsigned Ks16[FTK*KVW];
    __shared__ __align__(16) unsigned Vs16[FTK*KVW];

    const int t = threadIdx.x, lane = t & 31, w = t >> 5;
    const int g = lane >> 2, qt = lane & 3;
    const int bh = blockIdx.y;
    const int qbase = blockIdx.x * 256 + w * 32;

    const float scale = 0.17677669529663687f;
    const float* qp = g_q + ((size_t)bh * M_ + qbase) * DH_;

    unsigned qf[2][2][4];
#pragma unroll
    for (int mt = 0; mt < 2; mt++)
#pragma unroll
        for (int ks = 0; ks < 2; ks++) {
            int r0 = mt * 16 + g, c0 = ks * 16 + 2 * qt;
            qf[mt][ks][0] = pk16(scale*qp[r0*32 + c0],       scale*qp[r0*32 + c0 + 1]);
            qf[mt][ks][1] = pk16(scale*qp[(r0+8)*32 + c0],   scale*qp[(r0+8)*32 + c0 + 1]);
            qf[mt][ks][2] = pk16(scale*qp[r0*32 + c0 + 8],   scale*qp[r0*32 + c0 + 9]);
            qf[mt][ks][3] = pk16(scale*qp[(r0+8)*32 + c0+8], scale*qp[(r0+8)*32 + c0+9]);
        }

    float of[2][4][4];
#pragma unroll
    for (int i = 0; i < 2; i++)
#pragma unroll
        for (int j = 0; j < 4; j++)
#pragma unroll
            for (int r = 0; r < 4; r++) of[i][j][r] = 0.f;
    float mr[2][2] = {{-1e30f,-1e30f},{-1e30f,-1e30f}};
    float lr[2][2] = {{0.f,0.f},{0.f,0.f}};

    const float* kb = g_k + (size_t)bh * M_ * DH_;
    const float* vb = g_v + (size_t)bh * M_ * DH_;

    const unsigned vsbase = (unsigned)__cvta_generic_to_shared(Vs16);
    const int ldkr = (lane & 7) + 8 * ((lane >> 3) & 1);

    for (int kt = 0; kt < M_; kt += FTK) {
        __syncthreads();
#pragma unroll
        for (int p = 0; p < 2; p++) {
            int linear = p * 1024 + t * 4;
            int r = linear >> 5, c = linear & 31;
            float4 kv = *(const float4*)(kb + (size_t)(kt + r) * DH_ + c);
            Ks16[r*KVW + c/2]     = pk16(kv.x, kv.y);
            Ks16[r*KVW + c/2 + 1] = pk16(kv.z, kv.w);
            float4 vv = *(const float4*)(vb + (size_t)(kt + r) * DH_ + c);
            Vs16[r*KVW + c/2]     = pk16(vv.x, vv.y);
            Vs16[r*KVW + c/2 + 1] = pk16(vv.z, vv.w);
        }
        __syncthreads();

        float sf[2][8][4];
#pragma unroll
        for (int i = 0; i < 2; i++)
#pragma unroll
            for (int j = 0; j < 8; j++)
#pragma unroll
                for (int r = 0; r < 4; r++) sf[i][j][r] = 0.f;
#pragma unroll
        for (int ks = 0; ks < 2; ks++) {
            unsigned bfk[8][2];
            const int kw = ks * 8 + qt;
#pragma unroll
            for (int n = 0; n < 8; n++) {
                bfk[n][0] = Ks16[(n*8 + g)*KVW + kw];
                bfk[n][1] = Ks16[(n*8 + g)*KVW + kw + 4];
            }
#pragma unroll
            for (int mt = 0; mt < 2; mt++)
#pragma unroll
                for (int n = 0; n < 8; n++)
                    mma16(sf[mt][n], qf[mt][ks], bfk[n]);
        }

#pragma unroll
        for (int mt = 0; mt < 2; mt++) {
#pragma unroll
            for (int rh = 0; rh < 2; rh++) {
                float mx = -1e30f;
#pragma unroll
                for (int n = 0; n < 8; n++) {
                    mx = fmaxf(mx, sf[mt][n][rh*2]);
                    mx = fmaxf(mx, sf[mt][n][rh*2+1]);
                }
                mx = fmaxf(mx, __shfl_xor_sync(~0u, mx, 1));
                mx = fmaxf(mx, __shfl_xor_sync(~0u, mx, 2));
                float mn = fmaxf(mr[mt][rh], mx);
                float corr = __expf(mr[mt][rh] - mn);
                mr[mt][rh] = mn;
                lr[mt][rh] *= corr;
#pragma unroll
                for (int nd = 0; nd < 4; nd++) {
                    of[mt][nd][rh*2]   *= corr;
                    of[mt][nd][rh*2+1] *= corr;
                }
                float ls = 0.f;
#pragma unroll
                for (int n = 0; n < 8; n++) {
                    float e0 = __expf(sf[mt][n][rh*2]   - mn);
                    float e1 = __expf(sf[mt][n][rh*2+1] - mn);
                    ls += e0 + e1;
                    sf[mt][n][rh*2] = e0; sf[mt][n][rh*2+1] = e1;
                }
                lr[mt][rh] += ls;
            }
        }

#pragma unroll
        for (int j = 0; j < 4; j++) {
            unsigned bfv[4][2];
            const int kr = 16*j + ldkr;
#pragma unroll
            for (int nd = 0; nd < 4; nd++) {
                unsigned ad = vsbase + (unsigned)(kr * (KVW*4) + nd * 16);
                asm volatile(
                    "ldmatrix.sync.aligned.m8n8.x2.trans.shared.b16 {%0,%1},[%2];"
                    : "=r"(bfv[nd][0]), "=r"(bfv[nd][1]) : "r"(ad));
            }
#pragma unroll
            for (int mt = 0; mt < 2; mt++) {
                unsigned af[4];
                af[0] = pk16(sf[mt][2*j][0],   sf[mt][2*j][1]);
                af[1] = pk16(sf[mt][2*j][2],   sf[mt][2*j][3]);
                af[2] = pk16(sf[mt][2*j+1][0], sf[mt][2*j+1][1]);
                af[3] = pk16(sf[mt][2*j+1][2], sf[mt][2*j+1][3]);
#pragma unroll
                for (int nd = 0; nd < 4; nd++)
                    mma16(of[mt][nd], af, bfv[nd]);
            }
        }
    }

    const int b = bh >> 3, h = bh & 7;
#pragma unroll
    for (int mt = 0; mt < 2; mt++)
#pragma unroll
        for (int rh = 0; rh < 2; rh++) {
            float l = lr[mt][rh];
            l += __shfl_xor_sync(~0u, l, 1);
            l += __shfl_xor_sync(~0u, l, 2);
            float inv = 1.f / l;
            const int q = qbase + mt*16 + g + rh*8;
            float* op = g_attn + ((size_t)b * M_ + q) * D_ + h * DH_;
#pragma unroll
            for (int nd = 0; nd < 4; nd++)
                *(float2*)(op + nd*8 + 2*qt) =
                    make_float2(of[mt][nd][rh*2]*inv, of[mt][nd][rh*2+1]*inv);
        }
}

// ---------------- LayerNorm + residual -------------------------------------
__global__ void ln_residual(const float* __restrict__ prev,
                            const float* __restrict__ gamma,
                            const float* __restrict__ beta,
                            const float* __restrict__ alphap,
                            float* __restrict__ out)
{
    const int t = threadIdx.x, lane = t & 31, wid = t >> 5;
    const int row = blockIdx.x * 8 + wid;
    const float* x = g_ef2 + (size_t)row * D_;
    float xs[8], sum = 0.f, sq = 0.f;
#pragma unroll
    for (int c = 0; c < 8; c++) {
        float v = x[lane + c*32];
        xs[c] = v; sum += v; sq += v*v;
    }
#pragma unroll
    for (int off = 16; off; off >>= 1) {
        sum += __shfl_xor_sync(~0u, sum, off);
        sq  += __shfl_xor_sync(~0u, sq,  off);
    }
    const float mu   = sum * (1.f / D_);
    const float var  = sq * (1.f / D_) - mu * mu;
    const float rstd = rsqrtf(var + 1e-5f);
    const float alpha = *alphap;
#pragma unroll
    for (int c = 0; c < 8; c++) {
        int d = lane + c*32;
        float y = (xs[c] - mu) * rstd * gamma[d] + beta[d];
        size_t idx = (size_t)row * D_ + d;
        out[idx] = (1.f + alpha) * prev[idx] + (1.f - alpha) * y;
    }
}

// ---------------- launch ----------------------------------------------------
extern "C" void kernel_launch(void* const* d_in, const int* in_sizes, int n_in,
                              void* d_out, int out_size)
{
    const float* feature = (const float*)d_in[0];
    const float* inc     = (const float*)d_in[1];
    const float* prev    = (const float*)d_in[2];
    const float* inw     = (const float*)d_in[3];
    const float* inb     = (const float*)d_in[4];
    const float* outw    = (const float*)d_in[5];
    const float* outb    = (const float*)d_in[6];
    const float* projw   = (const float*)d_in[7];
    const float* gamma   = (const float*)d_in[8];
    const float* beta    = (const float*)d_in[9];
    const float* alphap  = (const float*)d_in[10];
    float* out = (float*)d_out;

    float *p_attn = 0, *p_attnout = 0, *p_ef2 = 0;
    cudaGetSymbolAddress((void**)&p_attn,    g_attn);
    cudaGetSymbolAddress((void**)&p_attnout, g_attnout);
    cudaGetSymbolAddress((void**)&p_ef2,     g_ef2);

    // 1. QKV projection -> scatter to q/k/v
    gemm_nt_f16<1><<<dim3(6, 64), 256>>>(feature, inw, inb, (float*)0, B_*M_, 3*D_, D_);
    // 2. attention (256-thr blocks, single wave)
    flash_attn_f16<<<dim3(8, 32), 256>>>();
    // 3. out_proj
    gemm_nt_f16<0><<<dim3(2, 64), 256>>>(p_attn, outw, outb, p_attnout, B_*M_, D_, D_);
    // 4. S^T = (inc^T @ attnout)^T  (split-K, A reg-prefetch pipeline)
    gemm_tn_S_f16<<<dim3(2, 8, B_*SPLITK), 256>>>(inc);
    // 5. fused reduce + softmax over e + ef = S*W
    softmax_fused<<<128, 256>>>();
    // 6. final projection (hybrid TN)
    gemm_proj_f16<<<dim3(2, 8, B_), 256>>>(projw, p_ef2);
    // 7. LN + residual mix
    ln_residual<<<512, 256>>>(prev, gamma, beta, alphap, out);
}